// round 1
// baseline (speedup 1.0000x reference)
#include <cuda_runtime.h>
#include <cuda_bf16.h>
#include <math.h>

// Problem constants (from reference): N_NODES = 1,000,000, N_ELEM = 2,000,000
#define MAX_NODES 1000000

// Scratch: per-node internal force accumulator (12 MB) + reduction accumulators.
__device__ float  g_Fint[3 * MAX_NODES];
__device__ double g_acc[2];   // [0] = sum(R_free^2), [1] = sum(F_free^2)

// ---------------------------------------------------------------------------
// Kernel 1: zero F_int and accumulators
// ---------------------------------------------------------------------------
__global__ void zero_kernel(int n3) {
    int i = blockIdx.x * blockDim.x + threadIdx.x;
    // vectorized zero via float4 where possible
    int n4 = n3 >> 2;                 // number of float4 chunks
    float4* p4 = reinterpret_cast<float4*>(g_Fint);
    if (i < n4) p4[i] = make_float4(0.f, 0.f, 0.f, 0.f);
    if (i == 0) {
        // tail elements
        for (int k = n4 * 4; k < n3; ++k) g_Fint[k] = 0.f;
        g_acc[0] = 0.0;
        g_acc[1] = 0.0;
    }
}

// ---------------------------------------------------------------------------
// Kernel 2: element pass — gather nodal displacements, compute local beam
// forces, scatter-add into g_Fint.
// ---------------------------------------------------------------------------
__global__ void elem_kernel(const float* __restrict__ pred_raw,
                            const float* __restrict__ u_c,
                            const float* __restrict__ theta_c,
                            const float* __restrict__ elem_len,
                            const float* __restrict__ prop_E,
                            const float* __restrict__ prop_A,
                            const float* __restrict__ prop_I,
                            const float* __restrict__ dirs,     // [E,3]
                            const int2*  __restrict__ conn,     // [E]
                            int E)
{
    int e = blockIdx.x * blockDim.x + threadIdx.x;
    if (e >= E) return;

    const float su = __ldg(u_c);       // uniform scalars; L1-resident
    const float st = __ldg(theta_c);

    int2 cn  = conn[e];
    int  nA  = cn.x;
    int  nB  = cn.y;

    float c  = __ldg(&dirs[3 * e + 0]);
    float s  = __ldg(&dirs[3 * e + 2]);
    float L  = elem_len[e];
    float pe = prop_E[e];
    float EA = pe * prop_A[e];
    float EI = pe * prop_I[e];

    // gather nodal displacement (scaled to physical units)
    float aAx = __ldg(&pred_raw[3 * nA + 0]) * su;
    float aAy = __ldg(&pred_raw[3 * nA + 1]) * su;
    float thA = -__ldg(&pred_raw[3 * nA + 2]) * st;
    float aBx = __ldg(&pred_raw[3 * nB + 0]) * su;
    float aBy = __ldg(&pred_raw[3 * nB + 1]) * su;
    float thB = -__ldg(&pred_raw[3 * nB + 2]) * st;

    // local frame
    float u_A =  c * aAx + s * aAy;
    float w_A = -s * aAx + c * aAy;
    float u_B =  c * aBx + s * aBy;
    float w_B = -s * aBx + c * aBy;

    float inv_l = 1.0f / L;
    float ea_l  = EA * inv_l;                 // AXIAL_WEIGHT = 1.0
    float ei_l  = EI * inv_l;
    float ei_l2 = ei_l * inv_l;
    float ei_l3 = ei_l2 * inv_l;

    float dw = w_A - w_B;
    float f0 = ea_l * (u_A - u_B);
    float f1 = 12.0f * ei_l3 * dw + 6.0f * ei_l2 * (thA + thB);
    float f2 = 6.0f * ei_l2 * dw + 4.0f * ei_l * thA + 2.0f * ei_l * thB;
    float f5 = 6.0f * ei_l2 * dw + 2.0f * ei_l * thA + 4.0f * ei_l * thB;

    float fAx = c * f0 - s * f1;
    float fAy = s * f0 + c * f1;
    float fAz = -f2;
    // f3 = -f0, f4 = -f1 -> fB rotates to exact negation in x,y
    float fBx = -fAx;
    float fBy = -fAy;
    float fBz = -f5;

    atomicAdd(&g_Fint[3 * nA + 0], fAx);
    atomicAdd(&g_Fint[3 * nA + 1], fAy);
    atomicAdd(&g_Fint[3 * nA + 2], fAz);
    atomicAdd(&g_Fint[3 * nB + 0], fBx);
    atomicAdd(&g_Fint[3 * nB + 1], fBy);
    atomicAdd(&g_Fint[3 * nB + 2], fBz);
}

// ---------------------------------------------------------------------------
// Kernel 3: node pass — masked residual reduction
// ---------------------------------------------------------------------------
__global__ void node_kernel(const float* __restrict__ F_ext,
                            const float* __restrict__ bc_disp,
                            const float* __restrict__ bc_rot,
                            int N)
{
    int i = blockIdx.x * blockDim.x + threadIdx.x;

    float r2 = 0.f, f2 = 0.f;
    if (i < N) {
        float md = 1.0f - bc_disp[i];
        float mr = 1.0f - bc_rot[i];

        float Fi0 = g_Fint[3 * i + 0];
        float Fi1 = g_Fint[3 * i + 1];
        float Fi2 = g_Fint[3 * i + 2];
        float Fe0 = F_ext[3 * i + 0];
        float Fe1 = F_ext[3 * i + 1];
        float Fe2 = F_ext[3 * i + 2];

        float R0 = (Fi0 - Fe0) * md;
        float R1 = (Fi1 - Fe1) * md;
        float R2 = (Fi2 - Fe2) * mr;
        float G0 = Fe0 * md;
        float G1 = Fe1 * md;
        float G2 = Fe2 * mr;

        r2 = R0 * R0 + R1 * R1 + R2 * R2;
        f2 = G0 * G0 + G1 * G1 + G2 * G2;
    }

    // warp reduce
    for (int off = 16; off > 0; off >>= 1) {
        r2 += __shfl_down_sync(0xffffffffu, r2, off);
        f2 += __shfl_down_sync(0xffffffffu, f2, off);
    }

    __shared__ float sr[32], sf[32];
    int lane = threadIdx.x & 31;
    int wid  = threadIdx.x >> 5;
    if (lane == 0) { sr[wid] = r2; sf[wid] = f2; }
    __syncthreads();

    if (wid == 0) {
        int nwarp = (blockDim.x + 31) >> 5;
        float rr = (lane < nwarp) ? sr[lane] : 0.f;
        float ff = (lane < nwarp) ? sf[lane] : 0.f;
        for (int off = 16; off > 0; off >>= 1) {
            rr += __shfl_down_sync(0xffffffffu, rr, off);
            ff += __shfl_down_sync(0xffffffffu, ff, off);
        }
        if (lane == 0) {
            atomicAdd(&g_acc[0], (double)rr);
            atomicAdd(&g_acc[1], (double)ff);
        }
    }
}

// ---------------------------------------------------------------------------
// Kernel 4: final divide
// ---------------------------------------------------------------------------
__global__ void final_kernel(float* out) {
    double fn = g_acc[1];
    if (fn < 1e-30) fn = 1e-30;
    out[0] = (float)(g_acc[0] / fn);
}

// ---------------------------------------------------------------------------
// Launch
// ---------------------------------------------------------------------------
extern "C" void kernel_launch(void* const* d_in, const int* in_sizes, int n_in,
                              void* d_out, int out_size)
{
    const float* pred_raw = (const float*)d_in[0];   // [N,3]
    const float* u_c      = (const float*)d_in[1];   // [1]
    const float* theta_c  = (const float*)d_in[2];   // [1]
    const float* elem_len = (const float*)d_in[3];   // [E]
    const float* prop_E   = (const float*)d_in[4];   // [E]
    const float* prop_A   = (const float*)d_in[5];   // [E]
    const float* prop_I   = (const float*)d_in[6];   // [E]
    const float* dirs     = (const float*)d_in[7];   // [E,3]
    const float* F_ext    = (const float*)d_in[8];   // [N,3]
    const float* bc_disp  = (const float*)d_in[9];   // [N,1]
    const float* bc_rot   = (const float*)d_in[10];  // [N,1]
    const int2*  conn     = (const int2*)d_in[11];   // [E,2]

    int N = in_sizes[0] / 3;
    int E = in_sizes[3];

    float* out = (float*)d_out;

    // Kernel 1: zero (3N floats, float4-vectorized)
    int n3 = 3 * N;
    int n4 = n3 >> 2;
    zero_kernel<<<(n4 + 255) / 256, 256>>>(n3);

    // Kernel 2: element scatter
    elem_kernel<<<(E + 255) / 256, 256>>>(pred_raw, u_c, theta_c, elem_len,
                                          prop_E, prop_A, prop_I, dirs, conn, E);

    // Kernel 3: node reduction
    node_kernel<<<(N + 255) / 256, 256>>>(F_ext, bc_disp, bc_rot, N);

    // Kernel 4: scalar divide
    final_kernel<<<1, 1>>>(out);
}

// round 2
// speedup vs baseline: 1.4923x; 1.4923x over previous
#include <cuda_runtime.h>
#include <cuda_bf16.h>
#include <math.h>

#define MAX_NODES 1000000

// Padded, pre-scaled nodal displacement: {ux*u_c, uy*u_c, th*theta_c, 0}
__device__ float4 g_pred4[MAX_NODES];
// Padded per-node internal force accumulator (w unused)
__device__ float4 g_Fint4[MAX_NODES];
__device__ double g_acc[2];   // [0] = sum(R_free^2), [1] = sum(F_free^2)

// ---------------------------------------------------------------------------
// Kernel 1: prep — scale/pad pred_raw into g_pred4, zero g_Fint4 and g_acc
// ---------------------------------------------------------------------------
__global__ void prep_kernel(const float* __restrict__ pred_raw,
                            const float* __restrict__ u_c,
                            const float* __restrict__ theta_c,
                            int N)
{
    int i = blockIdx.x * blockDim.x + threadIdx.x;
    if (i < N) {
        float su = __ldg(u_c);
        float st = __ldg(theta_c);
        float x = pred_raw[3 * i + 0];
        float y = pred_raw[3 * i + 1];
        float t = pred_raw[3 * i + 2];
        g_pred4[i] = make_float4(x * su, y * su, t * st, 0.f);
        g_Fint4[i] = make_float4(0.f, 0.f, 0.f, 0.f);
    }
    if (i == 0) { g_acc[0] = 0.0; g_acc[1] = 0.0; }
}

// ---------------------------------------------------------------------------
// Kernel 2: element pass — float4 gathers, vector RED scatter
// ---------------------------------------------------------------------------
__global__ void __launch_bounds__(256)
elem_kernel(const float* __restrict__ elem_len,
            const float* __restrict__ prop_E,
            const float* __restrict__ prop_A,
            const float* __restrict__ prop_I,
            const float* __restrict__ dirs,     // [E,3]
            const int2*  __restrict__ conn,     // [E]
            int E)
{
    __shared__ float sdir[3 * 256];
    int base = blockIdx.x * 256;

    // coalesced staging of dirs for this block's 256 elements
    int lim3 = 3 * E;
    #pragma unroll
    for (int k = 0; k < 3; ++k) {
        int t = threadIdx.x + k * 256;
        int g = base * 3 + t;
        sdir[t] = (g < lim3) ? dirs[g] : 0.f;
    }
    __syncthreads();

    int e = base + threadIdx.x;
    if (e >= E) return;

    float c = sdir[3 * threadIdx.x + 0];
    float s = sdir[3 * threadIdx.x + 2];

    int2 cn = conn[e];
    float L  = elem_len[e];
    float pe = prop_E[e];
    float EA = pe * prop_A[e];
    float EI = pe * prop_I[e];

    float4 dA = __ldg(&g_pred4[cn.x]);   // {ux, uy, th_scaled, 0}
    float4 dB = __ldg(&g_pred4[cn.y]);

    float thA = -dA.z;
    float thB = -dB.z;

    // local frame
    float u_A =  c * dA.x + s * dA.y;
    float w_A = -s * dA.x + c * dA.y;
    float u_B =  c * dB.x + s * dB.y;
    float w_B = -s * dB.x + c * dB.y;

    float inv_l = 1.0f / L;
    float ea_l  = EA * inv_l;
    float ei_l  = EI * inv_l;
    float ei_l2 = ei_l * inv_l;
    float ei_l3 = ei_l2 * inv_l;

    float dw = w_A - w_B;
    float f0 = ea_l * (u_A - u_B);
    float f1 = 12.0f * ei_l3 * dw + 6.0f * ei_l2 * (thA + thB);
    float f2 = 6.0f * ei_l2 * dw + 4.0f * ei_l * thA + 2.0f * ei_l * thB;
    float f5 = 6.0f * ei_l2 * dw + 2.0f * ei_l * thA + 4.0f * ei_l * thB;

    float fAx = c * f0 - s * f1;
    float fAy = s * f0 + c * f1;

    // vector reductions: one RED.128 per endpoint
    {
        float4* pA = &g_Fint4[cn.x];
        asm volatile("red.global.add.v4.f32 [%0], {%1, %2, %3, %4};"
                     :: "l"(pA), "f"(fAx), "f"(fAy), "f"(-f2), "f"(0.f)
                     : "memory");
        float4* pB = &g_Fint4[cn.y];
        asm volatile("red.global.add.v4.f32 [%0], {%1, %2, %3, %4};"
                     :: "l"(pB), "f"(-fAx), "f"(-fAy), "f"(-f5), "f"(0.f)
                     : "memory");
    }
}

// ---------------------------------------------------------------------------
// Kernel 3: node pass — masked residual reduction
// ---------------------------------------------------------------------------
__global__ void __launch_bounds__(256)
node_kernel(const float* __restrict__ F_ext,
            const float* __restrict__ bc_disp,
            const float* __restrict__ bc_rot,
            int N)
{
    int i = blockIdx.x * blockDim.x + threadIdx.x;

    float r2 = 0.f, f2 = 0.f;
    if (i < N) {
        float md = 1.0f - bc_disp[i];
        float mr = 1.0f - bc_rot[i];

        float4 Fi = g_Fint4[i];
        float Fe0 = F_ext[3 * i + 0];
        float Fe1 = F_ext[3 * i + 1];
        float Fe2 = F_ext[3 * i + 2];

        float R0 = (Fi.x - Fe0) * md;
        float R1 = (Fi.y - Fe1) * md;
        float R2 = (Fi.z - Fe2) * mr;
        float G0 = Fe0 * md;
        float G1 = Fe1 * md;
        float G2 = Fe2 * mr;

        r2 = R0 * R0 + R1 * R1 + R2 * R2;
        f2 = G0 * G0 + G1 * G1 + G2 * G2;
    }

    for (int off = 16; off > 0; off >>= 1) {
        r2 += __shfl_down_sync(0xffffffffu, r2, off);
        f2 += __shfl_down_sync(0xffffffffu, f2, off);
    }

    __shared__ float sr[8], sf[8];
    int lane = threadIdx.x & 31;
    int wid  = threadIdx.x >> 5;
    if (lane == 0) { sr[wid] = r2; sf[wid] = f2; }
    __syncthreads();

    if (wid == 0) {
        float rr = (lane < 8) ? sr[lane] : 0.f;
        float ff = (lane < 8) ? sf[lane] : 0.f;
        for (int off = 4; off > 0; off >>= 1) {
            rr += __shfl_down_sync(0xffffffffu, rr, off);
            ff += __shfl_down_sync(0xffffffffu, ff, off);
        }
        if (lane == 0) {
            atomicAdd(&g_acc[0], (double)rr);
            atomicAdd(&g_acc[1], (double)ff);
        }
    }
}

// ---------------------------------------------------------------------------
// Kernel 4: final divide
// ---------------------------------------------------------------------------
__global__ void final_kernel(float* out) {
    double fn = g_acc[1];
    if (fn < 1e-30) fn = 1e-30;
    out[0] = (float)(g_acc[0] / fn);
}

// ---------------------------------------------------------------------------
// Launch
// ---------------------------------------------------------------------------
extern "C" void kernel_launch(void* const* d_in, const int* in_sizes, int n_in,
                              void* d_out, int out_size)
{
    const float* pred_raw = (const float*)d_in[0];   // [N,3]
    const float* u_c      = (const float*)d_in[1];   // [1]
    const float* theta_c  = (const float*)d_in[2];   // [1]
    const float* elem_len = (const float*)d_in[3];   // [E]
    const float* prop_E   = (const float*)d_in[4];   // [E]
    const float* prop_A   = (const float*)d_in[5];   // [E]
    const float* prop_I   = (const float*)d_in[6];   // [E]
    const float* dirs     = (const float*)d_in[7];   // [E,3]
    const float* F_ext    = (const float*)d_in[8];   // [N,3]
    const float* bc_disp  = (const float*)d_in[9];   // [N,1]
    const float* bc_rot   = (const float*)d_in[10];  // [N,1]
    const int2*  conn     = (const int2*)d_in[11];   // [E,2]

    int N = in_sizes[0] / 3;
    int E = in_sizes[3];

    float* out = (float*)d_out;

    prep_kernel<<<(N + 255) / 256, 256>>>(pred_raw, u_c, theta_c, N);
    elem_kernel<<<(E + 255) / 256, 256>>>(elem_len, prop_E, prop_A, prop_I,
                                          dirs, conn, E);
    node_kernel<<<(N + 255) / 256, 256>>>(F_ext, bc_disp, bc_rot, N);
    final_kernel<<<1, 1>>>(out);
}